// round 1
// baseline (speedup 1.0000x reference)
#include <cuda_runtime.h>
#include <cuda_bf16.h>
#include <math.h>

#define TSEQ   2048
#define BATCH  4
#define NHEAD  16
#define DKH    64
#define DMODEL 1024
#define MTOT   (BATCH*TSEQ)   // 8192

// Scratch (allocation-free): Q/K/V in [b,h,t,dk], Y in [b,t, h*dk] (= [8192,1024])
__device__ float g_Q[BATCH*NHEAD*TSEQ*DKH];
__device__ float g_K[BATCH*NHEAD*TSEQ*DKH];
__device__ float g_V[BATCH*NHEAD*TSEQ*DKH];
__device__ float g_Y[MTOT*DMODEL];

// ---------------------------------------------------------------------------
// GEMM: C = A[M,K] @ W[N,K]^T, M=8192, N=K=1024.
// mode 0/1/2: A = Aparam (X), scatter-write into g_Q/g_K/g_V ([b,h,t,dk])
// mode 3:     A = g_Y, write Cparam row-major ([8192,1024])
// Tiling: 128x128x16, 256 threads, 8x8 per thread, register prefetch.
// ---------------------------------------------------------------------------
__global__ __launch_bounds__(256) void gemm_kernel(
    const float* __restrict__ Aparam, const float* __restrict__ W,
    float* __restrict__ Cparam, int mode)
{
    constexpr int BM = 128, BN = 128, BK = 16;
    constexpr int Kd = DMODEL, Nd = DMODEL;

    __shared__ float As[BK][BM + 4];
    __shared__ float Ws[BK][BN + 4];

    const float* A = (mode == 3) ? g_Y : Aparam;

    const int tid = threadIdx.x;
    const int tx = tid & 15;      // 0..15 -> output cols tx*8..tx*8+7
    const int ty = tid >> 4;      // 0..15 -> output rows ty*8..ty*8+7
    const int m0 = blockIdx.y * BM;
    const int n0 = blockIdx.x * BN;

    float acc[8][8];
#pragma unroll
    for (int i = 0; i < 8; i++)
#pragma unroll
        for (int j = 0; j < 8; j++) acc[i][j] = 0.0f;

    float4 pa[2], pw[2];

    // prefetch tile 0
#pragma unroll
    for (int l = 0; l < 2; l++) {
        int i = tid + 256 * l;
        int r = i >> 2, c = i & 3;
        pa[l] = *(const float4*)(A + (size_t)(m0 + r) * Kd + 0 * BK + c * 4);
        pw[l] = *(const float4*)(W + (size_t)(n0 + r) * Kd + 0 * BK + c * 4);
    }

    const int NT = Kd / BK;  // 64
    for (int kb = 0; kb < NT; kb++) {
        __syncthreads();
#pragma unroll
        for (int l = 0; l < 2; l++) {
            int i = tid + 256 * l;
            int r = i >> 2, c = i & 3;
            As[c * 4 + 0][r] = pa[l].x;
            As[c * 4 + 1][r] = pa[l].y;
            As[c * 4 + 2][r] = pa[l].z;
            As[c * 4 + 3][r] = pa[l].w;
            Ws[c * 4 + 0][r] = pw[l].x;
            Ws[c * 4 + 1][r] = pw[l].y;
            Ws[c * 4 + 2][r] = pw[l].z;
            Ws[c * 4 + 3][r] = pw[l].w;
        }
        __syncthreads();

        if (kb + 1 < NT) {
#pragma unroll
            for (int l = 0; l < 2; l++) {
                int i = tid + 256 * l;
                int r = i >> 2, c = i & 3;
                pa[l] = *(const float4*)(A + (size_t)(m0 + r) * Kd + (kb + 1) * BK + c * 4);
                pw[l] = *(const float4*)(W + (size_t)(n0 + r) * Kd + (kb + 1) * BK + c * 4);
            }
        }

#pragma unroll
        for (int kk = 0; kk < BK; kk++) {
            float a[8], b[8];
            *(float4*)(a + 0) = *(float4*)&As[kk][ty * 8 + 0];
            *(float4*)(a + 4) = *(float4*)&As[kk][ty * 8 + 4];
            *(float4*)(b + 0) = *(float4*)&Ws[kk][tx * 8 + 0];
            *(float4*)(b + 4) = *(float4*)&Ws[kk][tx * 8 + 4];
#pragma unroll
            for (int i = 0; i < 8; i++)
#pragma unroll
                for (int j = 0; j < 8; j++) acc[i][j] += a[i] * b[j];
        }
    }

    if (mode == 3) {
#pragma unroll
        for (int i = 0; i < 8; i++) {
            float* dst = Cparam + (size_t)(m0 + ty * 8 + i) * Nd + n0 + tx * 8;
            *(float4*)(dst + 0) = make_float4(acc[i][0], acc[i][1], acc[i][2], acc[i][3]);
            *(float4*)(dst + 4) = make_float4(acc[i][4], acc[i][5], acc[i][6], acc[i][7]);
        }
    } else {
        float* base = (mode == 0) ? g_Q : (mode == 1) ? g_K : g_V;
        int n = n0 + tx * 8;
        int h = n >> 6;          // head
        int dk0 = n & 63;        // within-head offset (multiple of 8)
#pragma unroll
        for (int i = 0; i < 8; i++) {
            int m = m0 + ty * 8 + i;
            int b = m >> 11;             // / TSEQ
            int t = m & (TSEQ - 1);
            float* dst = base + ((size_t)(b * NHEAD + h) * TSEQ + t) * DKH + dk0;
            *(float4*)(dst + 0) = make_float4(acc[i][0], acc[i][1], acc[i][2], acc[i][3]);
            *(float4*)(dst + 4) = make_float4(acc[i][4], acc[i][5], acc[i][6], acc[i][7]);
        }
    }
}

// ---------------------------------------------------------------------------
// Flash attention: per (b,h), BM=64 query rows per block, BN=32 key block,
// dk=64, online softmax. 256 threads: (ty=tid/16) owns rows ty*4..+3,
// (tx=tid%16): S cols tx & tx+16, O cols 4*tx..+3. Writes Y in [b,t,h*dk].
// ---------------------------------------------------------------------------
__global__ __launch_bounds__(256) void attn_kernel()
{
    __shared__ float Qs[64][64];   // broadcast reads -> no pad needed
    __shared__ float Ks[32][68];   // padded: 4*tx bank spread on LDS.128
    __shared__ float Vs[32][64];
    __shared__ float Ps[64][36];   // padded stride 36: conflict-free scalar rw

    const int tid = threadIdx.x;
    const int tx = tid & 15;
    const int ty = tid >> 4;
    const int bh = blockIdx.y;                 // 0..63
    const int q0 = blockIdx.x * 64;

    const float* Qp = g_Q + ((size_t)bh * TSEQ + q0) * DKH;
    const float* Kp = g_K + (size_t)bh * TSEQ * DKH;
    const float* Vp = g_V + (size_t)bh * TSEQ * DKH;

    // Load Q tile, folding in softmax scale 1/sqrt(64) = 0.125
#pragma unroll
    for (int l = 0; l < 4; l++) {
        int i = tid + l * 256;       // 1024 float4 total
        int r = i >> 4, c4 = i & 15;
        float4 v = *(const float4*)(Qp + r * 64 + c4 * 4);
        v.x *= 0.125f; v.y *= 0.125f; v.z *= 0.125f; v.w *= 0.125f;
        *(float4*)&Qs[r][c4 * 4] = v;
    }

    float o[4][4];
    float mi[4], li[4];
#pragma unroll
    for (int i = 0; i < 4; i++) {
        mi[i] = -1e30f; li[i] = 0.0f;
#pragma unroll
        for (int u = 0; u < 4; u++) o[i][u] = 0.0f;
    }

    for (int kt = 0; kt < TSEQ / 32; kt++) {
        __syncthreads();   // previous iteration fully done (Ps/Vs consumed)
#pragma unroll
        for (int l = 0; l < 2; l++) {
            int i = tid + l * 256;   // 512 float4 per tile
            int r = i >> 4, c4 = i & 15;
            *(float4*)&Ks[r][c4 * 4] = *(const float4*)(Kp + (size_t)(kt * 32 + r) * 64 + c4 * 4);
            *(float4*)&Vs[r][c4 * 4] = *(const float4*)(Vp + (size_t)(kt * 32 + r) * 64 + c4 * 4);
        }
        __syncthreads();

        // S = (Q*scale) @ K^T   -> s[i][j], cols c = tx + 16*j
        float s[4][2];
#pragma unroll
        for (int i = 0; i < 4; i++) { s[i][0] = 0.0f; s[i][1] = 0.0f; }
#pragma unroll
        for (int k4 = 0; k4 < 16; k4++) {
            float4 kv0 = *(float4*)&Ks[tx][k4 * 4];
            float4 kv1 = *(float4*)&Ks[tx + 16][k4 * 4];
#pragma unroll
            for (int i = 0; i < 4; i++) {
                float4 qv = *(float4*)&Qs[ty * 4 + i][k4 * 4];
                s[i][0] += qv.x * kv0.x + qv.y * kv0.y + qv.z * kv0.z + qv.w * kv0.w;
                s[i][1] += qv.x * kv1.x + qv.y * kv1.y + qv.z * kv1.z + qv.w * kv1.w;
            }
        }

        // Online softmax update (row groups = 16 lanes sharing ty)
#pragma unroll
        for (int i = 0; i < 4; i++) {
            float mt = fmaxf(s[i][0], s[i][1]);
#pragma unroll
            for (int d = 1; d < 16; d <<= 1)
                mt = fmaxf(mt, __shfl_xor_sync(0xffffffffu, mt, d));
            float mn = fmaxf(mi[i], mt);
            float corr = __expf(mi[i] - mn);
            mi[i] = mn;
            float p0 = __expf(s[i][0] - mn);
            float p1 = __expf(s[i][1] - mn);
            s[i][0] = p0; s[i][1] = p1;
            float rs = p0 + p1;
#pragma unroll
            for (int d = 1; d < 16; d <<= 1)
                rs += __shfl_xor_sync(0xffffffffu, rs, d);
            li[i] = li[i] * corr + rs;
            o[i][0] *= corr; o[i][1] *= corr; o[i][2] *= corr; o[i][3] *= corr;
        }

        // Stage P to smem (prev readers already synced at top of loop)
#pragma unroll
        for (int i = 0; i < 4; i++) {
            Ps[ty * 4 + i][tx]      = s[i][0];
            Ps[ty * 4 + i][tx + 16] = s[i][1];
        }
        __syncthreads();

        // O += P @ V   (O cols n = 4*tx..+3)
#pragma unroll 8
        for (int c = 0; c < 32; c++) {
            float4 vv = *(float4*)&Vs[c][tx * 4];
#pragma unroll
            for (int i = 0; i < 4; i++) {
                float pr = Ps[ty * 4 + i][c];
                o[i][0] += pr * vv.x;
                o[i][1] += pr * vv.y;
                o[i][2] += pr * vv.z;
                o[i][3] += pr * vv.w;
            }
        }
    }

    // Epilogue: Y[b, t, h*64 + n] = o / l
    const int b = bh >> 4, h = bh & 15;
#pragma unroll
    for (int i = 0; i < 4; i++) {
        float inv = 1.0f / li[i];
        int t = q0 + ty * 4 + i;
        float4 ov = make_float4(o[i][0] * inv, o[i][1] * inv, o[i][2] * inv, o[i][3] * inv);
        *(float4*)(g_Y + (size_t)(b * TSEQ + t) * DMODEL + h * DKH + tx * 4) = ov;
    }
}

// ---------------------------------------------------------------------------
extern "C" void kernel_launch(void* const* d_in, const int* in_sizes, int n_in,
                              void* d_out, int out_size)
{
    const float* X  = (const float*)d_in[0];
    const float* Wq = (const float*)d_in[1];
    const float* Wk = (const float*)d_in[2];
    const float* Wv = (const float*)d_in[3];
    const float* Wo = (const float*)d_in[4];
    float* out = (float*)d_out;

    dim3 gg(DMODEL / 128, MTOT / 128);   // (8, 64)
    gemm_kernel<<<gg, 256>>>(X, Wq, out, 0);   // -> g_Q
    gemm_kernel<<<gg, 256>>>(X, Wk, out, 1);   // -> g_K
    gemm_kernel<<<gg, 256>>>(X, Wv, out, 2);   // -> g_V

    attn_kernel<<<dim3(TSEQ / 64, BATCH * NHEAD), 256>>>();   // -> g_Y

    gemm_kernel<<<gg, 256>>>(X, Wo, out, 3);   // g_Y @ Wo^T -> out
}

// round 3
// speedup vs baseline: 1.3909x; 1.3909x over previous
#include <cuda_runtime.h>
#include <cuda_bf16.h>
#include <math.h>
#include <stdint.h>

#define TSEQ   2048
#define BATCH  4
#define NHEAD  16
#define DKH    64
#define DMODEL 1024
#define MTOT   (BATCH*TSEQ)   // 8192

// Scratch (allocation-free device globals)
__device__ float    g_Q[BATCH*NHEAD*TSEQ*DKH];
__device__ float    g_K[BATCH*NHEAD*TSEQ*DKH];
__device__ float    g_V[BATCH*NHEAD*TSEQ*DKH];
__device__ float    g_Y[MTOT*DMODEL];
__device__ uint32_t g_Xc[MTOT*DMODEL];          // X  as tf32 (rna)
__device__ uint32_t g_Wc[4][DMODEL*DMODEL];     // Wq,Wk,Wv,Wo as tf32
__device__ uint32_t g_Yc[MTOT*DMODEL];          // Y  as tf32

__device__ __forceinline__ uint32_t smem_u32(const void* p) {
    uint32_t a;
    asm("{ .reg .u64 t; cvta.to.shared.u64 t, %1; cvt.u32.u64 %0, t; }" : "=r"(a) : "l"(p));
    return a;
}
__device__ __forceinline__ uint32_t f2tf32(float f) {
    uint32_t r;
    asm("cvt.rna.tf32.f32 %0, %1;" : "=r"(r) : "f"(f));
    return r;
}
__device__ __forceinline__ void cp16(uint32_t dst, const void* src) {
    asm volatile("cp.async.cg.shared.global [%0], [%1], 16;" :: "r"(dst), "l"(src));
}
#define CP_COMMIT() asm volatile("cp.async.commit_group;" ::: "memory")
#define CP_WAIT0()  asm volatile("cp.async.wait_group 0;" ::: "memory")

__device__ __forceinline__ void mma_tf32(float c[4], const uint32_t a[4], const uint32_t b[2]) {
    asm volatile(
        "mma.sync.aligned.m16n8k8.row.col.f32.tf32.tf32.f32 "
        "{%0,%1,%2,%3}, {%4,%5,%6,%7}, {%8,%9}, {%0,%1,%2,%3};"
        : "+f"(c[0]), "+f"(c[1]), "+f"(c[2]), "+f"(c[3])
        : "r"(a[0]), "r"(a[1]), "r"(a[2]), "r"(a[3]), "r"(b[0]), "r"(b[1]));
}

// ===========================================================================
// Elementwise fp32 -> tf32 (rna) conversion. which: 0=X->g_Xc, 1..4=W->g_Wc,
// 5=g_Y->g_Yc (in ignored).
// ===========================================================================
__global__ __launch_bounds__(256) void conv_tf32(const float* __restrict__ in, int which, int n)
{
    uint32_t* out = (which == 0) ? g_Xc : (which <= 4) ? g_Wc[which - 1] : g_Yc;
    const float* src = (which == 5) ? g_Y : in;
    int i = (blockIdx.x * 256 + threadIdx.x) * 4;
    if (i < n) {
        float4 v = *(const float4*)(src + i);
        *(uint4*)(out + i) = make_uint4(f2tf32(v.x), f2tf32(v.y), f2tf32(v.z), f2tf32(v.w));
    }
}

// ===========================================================================
// tf32 mma.sync GEMM: C = A[8192,1024] @ W[1024,1024]^T  (both tf32, K-major)
// CTA 128x128, BK=16, double-buffered cp.async. 8 warps as 2(m) x 4(n),
// warp tile 64x32 -> 4x4 m16n8k8 tiles.
// mode 0/1/2: scatter into g_Q/g_K/g_V ([b,h,t,dk]); mode 3: row-major out.
// ===========================================================================
#define SSTRIDE 20   // 16 + 4 pad floats: conflict-free frags, 16B-aligned rows

__global__ __launch_bounds__(256) void tc_gemm(float* __restrict__ Cout, int mode)
{
    __shared__ uint32_t As[2][128 * SSTRIDE];
    __shared__ uint32_t Bs[2][128 * SSTRIDE];

    const uint32_t* A = (mode == 3) ? g_Yc : g_Xc;
    const uint32_t* W = g_Wc[mode];

    const int tid  = threadIdx.x;
    const int wid  = tid >> 5, lane = tid & 31;
    const int g    = lane >> 2, t = lane & 3;
    const int wm   = (wid >> 2) * 64;    // 0 or 64
    const int wn   = (wid & 3) * 32;     // 0,32,64,96
    const int m0   = blockIdx.y * 128;
    const int n0   = blockIdx.x * 128;

    const uint32_t sA = smem_u32(As);
    const uint32_t sB = smem_u32(Bs);
    const int r0 = tid >> 2, c4 = tid & 3;   // staging: 64 rows/pass, 4 x 16B cols

    float acc[4][4][4];
#pragma unroll
    for (int i = 0; i < 4; i++)
#pragma unroll
        for (int j = 0; j < 4; j++)
#pragma unroll
            for (int u = 0; u < 4; u++) acc[i][j][u] = 0.0f;

    auto stage = [&](int kb, int p) {
#pragma unroll
        for (int h = 0; h < 2; h++) {
            int row = r0 + h * 64;
            cp16(sA + (p * 128 * SSTRIDE + row * SSTRIDE + c4 * 4) * 4,
                 A + (size_t)(m0 + row) * DMODEL + kb * 16 + c4 * 4);
            cp16(sB + (p * 128 * SSTRIDE + row * SSTRIDE + c4 * 4) * 4,
                 W + (size_t)(n0 + row) * DMODEL + kb * 16 + c4 * 4);
        }
        CP_COMMIT();
    };

    stage(0, 0);

    const int NT = DMODEL / 16;  // 64
    for (int kb = 0; kb < NT; kb++) {
        const int p = kb & 1;
        CP_WAIT0();
        __syncthreads();                 // buf p full; all warps past compute(p^1)
        if (kb + 1 < NT) stage(kb + 1, p ^ 1);

        const uint32_t* as = As[p];
        const uint32_t* bs = Bs[p];
#pragma unroll
        for (int k8 = 0; k8 < 2; k8++) {
            uint32_t a[4][4], b[4][2];
#pragma unroll
            for (int mt = 0; mt < 4; mt++) {
                int rb = wm + mt * 16;
                a[mt][0] = as[(rb + g) * SSTRIDE + k8 * 8 + t];
                a[mt][1] = as[(rb + g + 8) * SSTRIDE + k8 * 8 + t];
                a[mt][2] = as[(rb + g) * SSTRIDE + k8 * 8 + t + 4];
                a[mt][3] = as[(rb + g + 8) * SSTRIDE + k8 * 8 + t + 4];
            }
#pragma unroll
            for (int nt = 0; nt < 4; nt++) {
                int nb = wn + nt * 8;
                b[nt][0] = bs[(nb + g) * SSTRIDE + k8 * 8 + t];
                b[nt][1] = bs[(nb + g) * SSTRIDE + k8 * 8 + t + 4];
            }
#pragma unroll
            for (int mt = 0; mt < 4; mt++)
#pragma unroll
                for (int nt = 0; nt < 4; nt++)
                    mma_tf32(acc[mt][nt], a[mt], b[nt]);
        }
        __syncthreads();                 // done reading buf p before it refills
    }

    // Epilogue. c0,c1: (row g, cols 2t,2t+1); c2,c3: row g+8.
#pragma unroll
    for (int mt = 0; mt < 4; mt++) {
#pragma unroll
        for (int h = 0; h < 2; h++) {
            int m = m0 + wm + mt * 16 + g + h * 8;
#pragma unroll
            for (int nt = 0; nt < 4; nt++) {
                int n = n0 + wn + nt * 8 + 2 * t;
                float2 v = make_float2(acc[mt][nt][h * 2 + 0], acc[mt][nt][h * 2 + 1]);
                if (mode == 3) {
                    *(float2*)(Cout + (size_t)m * DMODEL + n) = v;
                } else {
                    float* base = (mode == 0) ? g_Q : (mode == 1) ? g_K : g_V;
                    int hh = n >> 6, dk0 = n & 63;
                    int b = m >> 11, tt = m & (TSEQ - 1);
                    *(float2*)(base + ((size_t)(b * NHEAD + hh) * TSEQ + tt) * DKH + dk0) = v;
                }
            }
        }
    }
}

// ---------------------------------------------------------------------------
// Flash attention (unchanged, proven): per (b,h), 64 q-rows/block, 32-key
// blocks, online softmax. Writes Y in [b,t,h*dk].
// ---------------------------------------------------------------------------
__global__ __launch_bounds__(256) void attn_kernel()
{
    __shared__ float Qs[64][64];
    __shared__ float Ks[32][68];
    __shared__ float Vs[32][64];
    __shared__ float Ps[64][36];

    const int tid = threadIdx.x;
    const int tx = tid & 15;
    const int ty = tid >> 4;
    const int bh = blockIdx.y;
    const int q0 = blockIdx.x * 64;

    const float* Qp = g_Q + ((size_t)bh * TSEQ + q0) * DKH;
    const float* Kp = g_K + (size_t)bh * TSEQ * DKH;
    const float* Vp = g_V + (size_t)bh * TSEQ * DKH;

#pragma unroll
    for (int l = 0; l < 4; l++) {
        int i = tid + l * 256;
        int r = i >> 4, c4 = i & 15;
        float4 v = *(const float4*)(Qp + r * 64 + c4 * 4);
        v.x *= 0.125f; v.y *= 0.125f; v.z *= 0.125f; v.w *= 0.125f;
        *(float4*)&Qs[r][c4 * 4] = v;
    }

    float o[4][4];
    float mi[4], li[4];
#pragma unroll
    for (int i = 0; i < 4; i++) {
        mi[i] = -1e30f; li[i] = 0.0f;
#pragma unroll
        for (int u = 0; u < 4; u++) o[i][u] = 0.0f;
    }

    for (int kt = 0; kt < TSEQ / 32; kt++) {
        __syncthreads();
#pragma unroll
        for (int l = 0; l < 2; l++) {
            int i = tid + l * 256;
            int r = i >> 4, c4 = i & 15;
            *(float4*)&Ks[r][c4 * 4] = *(const float4*)(Kp + (size_t)(kt * 32 + r) * 64 + c4 * 4);
            *(float4*)&Vs[r][c4 * 4] = *(const float4*)(Vp + (size_t)(kt * 32 + r) * 64 + c4 * 4);
        }
        __syncthreads();

        float s[4][2];
#pragma unroll
        for (int i = 0; i < 4; i++) { s[i][0] = 0.0f; s[i][1] = 0.0f; }
#pragma unroll
        for (int k4 = 0; k4 < 16; k4++) {
            float4 kv0 = *(float4*)&Ks[tx][k4 * 4];
            float4 kv1 = *(float4*)&Ks[tx + 16][k4 * 4];
#pragma unroll
            for (int i = 0; i < 4; i++) {
                float4 qv = *(float4*)&Qs[ty * 4 + i][k4 * 4];
                s[i][0] += qv.x * kv0.x + qv.y * kv0.y + qv.z * kv0.z + qv.w * kv0.w;
                s[i][1] += qv.x * kv1.x + qv.y * kv1.y + qv.z * kv1.z + qv.w * kv1.w;
            }
        }

#pragma unroll
        for (int i = 0; i < 4; i++) {
            float mt = fmaxf(s[i][0], s[i][1]);
#pragma unroll
            for (int d = 1; d < 16; d <<= 1)
                mt = fmaxf(mt, __shfl_xor_sync(0xffffffffu, mt, d));
            float mn = fmaxf(mi[i], mt);
            float corr = __expf(mi[i] - mn);
            mi[i] = mn;
            float p0 = __expf(s[i][0] - mn);
            float p1 = __expf(s[i][1] - mn);
            s[i][0] = p0; s[i][1] = p1;
            float rs = p0 + p1;
#pragma unroll
            for (int d = 1; d < 16; d <<= 1)
                rs += __shfl_xor_sync(0xffffffffu, rs, d);
            li[i] = li[i] * corr + rs;
            o[i][0] *= corr; o[i][1] *= corr; o[i][2] *= corr; o[i][3] *= corr;
        }

#pragma unroll
        for (int i = 0; i < 4; i++) {
            Ps[ty * 4 + i][tx]      = s[i][0];
            Ps[ty * 4 + i][tx + 16] = s[i][1];
        }
        __syncthreads();

#pragma unroll 8
        for (int c = 0; c < 32; c++) {
            float4 vv = *(float4*)&Vs[c][tx * 4];
#pragma unroll
            for (int i = 0; i < 4; i++) {
                float pr = Ps[ty * 4 + i][c];
                o[i][0] += pr * vv.x;
                o[i][1] += pr * vv.y;
                o[i][2] += pr * vv.z;
                o[i][3] += pr * vv.w;
            }
        }
    }

    const int b = bh >> 4, h = bh & 15;
#pragma unroll
    for (int i = 0; i < 4; i++) {
        float inv = 1.0f / li[i];
        int t = q0 + ty * 4 + i;
        float4 ov = make_float4(o[i][0] * inv, o[i][1] * inv, o[i][2] * inv, o[i][3] * inv);
        *(float4*)(g_Y + (size_t)(b * TSEQ + t) * DMODEL + h * DKH + tx * 4) = ov;
    }
}

// ---------------------------------------------------------------------------
extern "C" void kernel_launch(void* const* d_in, const int* in_sizes, int n_in,
                              void* d_out, int out_size)
{
    const float* X  = (const float*)d_in[0];
    const float* Wq = (const float*)d_in[1];
    const float* Wk = (const float*)d_in[2];
    const float* Wv = (const float*)d_in[3];
    const float* Wo = (const float*)d_in[4];
    float* out = (float*)d_out;

    const int nX = MTOT * DMODEL, nW = DMODEL * DMODEL;
    conv_tf32<<<nX / 1024, 256>>>(X,  0, nX);
    conv_tf32<<<nW / 1024, 256>>>(Wq, 1, nW);
    conv_tf32<<<nW / 1024, 256>>>(Wk, 2, nW);
    conv_tf32<<<nW / 1024, 256>>>(Wv, 3, nW);
    conv_tf32<<<nW / 1024, 256>>>(Wo, 4, nW);

    dim3 gg(DMODEL / 128, MTOT / 128);   // (8, 64)
    tc_gemm<<<gg, 256>>>(out, 0);   // -> g_Q
    tc_gemm<<<gg, 256>>>(out, 1);   // -> g_K
    tc_gemm<<<gg, 256>>>(out, 2);   // -> g_V

    attn_kernel<<<dim3(TSEQ / 64, BATCH * NHEAD), 256>>>();   // -> g_Y

    conv_tf32<<<nX / 1024, 256>>>(nullptr, 5, nX);   // g_Y -> g_Yc
    tc_gemm<<<gg, 256>>>(out, 3);   // Yc @ Wo^T -> out
}

// round 5
// speedup vs baseline: 3.2777x; 2.3565x over previous
#include <cuda_runtime.h>
#include <cuda_bf16.h>
#include <math.h>
#include <stdint.h>

#define TSEQ   2048
#define BATCH  4
#define NHEAD  16
#define DKH    64
#define DMODEL 1024
#define MTOT   (BATCH*TSEQ)   // 8192

// Scratch (allocation-free device globals). Q/K/V stored as tf32 bits,
// [b,h,t,dk]; Q pre-scaled by 0.125. Yc = attention output as tf32 [b,t,1024].
__device__ uint32_t g_Q[BATCH*NHEAD*TSEQ*DKH];
__device__ uint32_t g_K[BATCH*NHEAD*TSEQ*DKH];
__device__ uint32_t g_V[BATCH*NHEAD*TSEQ*DKH];
__device__ uint32_t g_Xc[MTOT*DMODEL];          // X  as tf32 (rna)
__device__ uint32_t g_Wc[4][DMODEL*DMODEL];     // Wq,Wk,Wv,Wo as tf32
__device__ uint32_t g_Yc[MTOT*DMODEL];          // attention out as tf32

__device__ __forceinline__ uint32_t smem_u32(const void* p) {
    uint32_t a;
    asm("{ .reg .u64 t; cvta.to.shared.u64 t, %1; cvt.u32.u64 %0, t; }" : "=r"(a) : "l"(p));
    return a;
}
__device__ __forceinline__ uint32_t f2tf32(float f) {
    uint32_t r;
    asm("cvt.rna.tf32.f32 %0, %1;" : "=r"(r) : "f"(f));
    return r;
}
__device__ __forceinline__ void cp16(uint32_t dst, const void* src) {
    asm volatile("cp.async.cg.shared.global [%0], [%1], 16;" :: "r"(dst), "l"(src));
}
#define CP_COMMIT() asm volatile("cp.async.commit_group;" ::: "memory")
#define CP_WAIT0()  asm volatile("cp.async.wait_group 0;" ::: "memory")
#define CP_WAIT1()  asm volatile("cp.async.wait_group 1;" ::: "memory")

__device__ __forceinline__ void mma_tf32(float c[4], const uint32_t a[4], const uint32_t b[2]) {
    asm volatile(
        "mma.sync.aligned.m16n8k8.row.col.f32.tf32.tf32.f32 "
        "{%0,%1,%2,%3}, {%4,%5,%6,%7}, {%8,%9}, {%0,%1,%2,%3};"
        : "+f"(c[0]), "+f"(c[1]), "+f"(c[2]), "+f"(c[3])
        : "r"(a[0]), "r"(a[1]), "r"(a[2]), "r"(a[3]), "r"(b[0]), "r"(b[1]));
}

// ===========================================================================
// Elementwise fp32 -> tf32 (rna). which: 0=X->g_Xc, 1..4=W->g_Wc[which-1].
// ===========================================================================
__global__ __launch_bounds__(256) void conv_tf32(const float* __restrict__ in, int which, int n)
{
    uint32_t* out = (which == 0) ? g_Xc : g_Wc[which - 1];
    int i = (blockIdx.x * 256 + threadIdx.x) * 4;
    if (i < n) {
        float4 v = *(const float4*)(in + i);
        *(uint4*)(out + i) = make_uint4(f2tf32(v.x), f2tf32(v.y), f2tf32(v.z), f2tf32(v.w));
    }
}

// ===========================================================================
// tf32 mma.sync GEMM (proven round 3): C = A[8192,1024] @ W[1024,1024]^T
// CTA 128x128, BK=16, double-buffered cp.async. 8 warps 2(m)x4(n), 64x32 warp.
// mode 0/1/2: tf32 scatter into g_Q/g_K/g_V (Q scaled 0.125); mode 3: fp32 out.
// ===========================================================================
#define SSTRIDE 20

__global__ __launch_bounds__(256) void tc_gemm(float* __restrict__ Cout, int mode)
{
    __shared__ uint32_t As[2][128 * SSTRIDE];
    __shared__ uint32_t Bs[2][128 * SSTRIDE];

    const uint32_t* A = (mode == 3) ? g_Yc : g_Xc;
    const uint32_t* W = g_Wc[mode];

    const int tid  = threadIdx.x;
    const int wid  = tid >> 5, lane = tid & 31;
    const int g    = lane >> 2, t = lane & 3;
    const int wm   = (wid >> 2) * 64;
    const int wn   = (wid & 3) * 32;
    const int m0   = blockIdx.y * 128;
    const int n0   = blockIdx.x * 128;

    const uint32_t sA = smem_u32(As);
    const uint32_t sB = smem_u32(Bs);
    const int r0 = tid >> 2, c4 = tid & 3;

    float acc[4][4][4];
#pragma unroll
    for (int i = 0; i < 4; i++)
#pragma unroll
        for (int j = 0; j < 4; j++)
#pragma unroll
            for (int u = 0; u < 4; u++) acc[i][j][u] = 0.0f;

    auto stage = [&](int kb, int p) {
#pragma unroll
        for (int h = 0; h < 2; h++) {
            int row = r0 + h * 64;
            cp16(sA + (p * 128 * SSTRIDE + row * SSTRIDE + c4 * 4) * 4,
                 A + (size_t)(m0 + row) * DMODEL + kb * 16 + c4 * 4);
            cp16(sB + (p * 128 * SSTRIDE + row * SSTRIDE + c4 * 4) * 4,
                 W + (size_t)(n0 + row) * DMODEL + kb * 16 + c4 * 4);
        }
        CP_COMMIT();
    };

    stage(0, 0);

    const int NT = DMODEL / 16;
    for (int kb = 0; kb < NT; kb++) {
        const int p = kb & 1;
        CP_WAIT0();
        __syncthreads();
        if (kb + 1 < NT) stage(kb + 1, p ^ 1);

        const uint32_t* as = As[p];
        const uint32_t* bs = Bs[p];
#pragma unroll
        for (int k8 = 0; k8 < 2; k8++) {
            uint32_t a[4][4], b[4][2];
#pragma unroll
            for (int mt = 0; mt < 4; mt++) {
                int rb = wm + mt * 16;
                a[mt][0] = as[(rb + g) * SSTRIDE + k8 * 8 + t];
                a[mt][1] = as[(rb + g + 8) * SSTRIDE + k8 * 8 + t];
                a[mt][2] = as[(rb + g) * SSTRIDE + k8 * 8 + t + 4];
                a[mt][3] = as[(rb + g + 8) * SSTRIDE + k8 * 8 + t + 4];
            }
#pragma unroll
            for (int nt = 0; nt < 4; nt++) {
                int nb = wn + nt * 8;
                b[nt][0] = bs[(nb + g) * SSTRIDE + k8 * 8 + t];
                b[nt][1] = bs[(nb + g) * SSTRIDE + k8 * 8 + t + 4];
            }
#pragma unroll
            for (int mt = 0; mt < 4; mt++)
#pragma unroll
                for (int nt = 0; nt < 4; nt++)
                    mma_tf32(acc[mt][nt], a[mt], b[nt]);
        }
        __syncthreads();
    }

#pragma unroll
    for (int mt = 0; mt < 4; mt++) {
#pragma unroll
        for (int h = 0; h < 2; h++) {
            int m = m0 + wm + mt * 16 + g + h * 8;
#pragma unroll
            for (int nt = 0; nt < 4; nt++) {
                int n = n0 + wn + nt * 8 + 2 * t;
                float vx = acc[mt][nt][h * 2 + 0];
                float vy = acc[mt][nt][h * 2 + 1];
                if (mode == 3) {
                    *(float2*)(Cout + (size_t)m * DMODEL + n) = make_float2(vx, vy);
                } else {
                    if (mode == 0) { vx *= 0.125f; vy *= 0.125f; }
                    uint32_t* base = (mode == 0) ? g_Q : (mode == 1) ? g_K : g_V;
                    int hh = n >> 6, dk0 = n & 63;
                    int b = m >> 11, tt = m & (TSEQ - 1);
                    *(uint2*)(base + ((size_t)(b * NHEAD + hh) * TSEQ + tt) * DKH + dk0)
                        = make_uint2(f2tf32(vx), f2tf32(vy));
                }
            }
        }
    }
}

// ===========================================================================
// Tensor-core flash attention: per (b,h), BM=64 q rows (4 warps x m16),
// BN=32 keys/iter, dk=64. Q frags persistent; online softmax fp32;
// P staged via smem as tf32; O fp32 in registers. Writes g_Yc (tf32).
// ===========================================================================
#define KSTR 68
#define VSTR 72
#define PSTR 36

__global__ __launch_bounds__(128) void attn_mma()
{
    __shared__ uint32_t Ks[2][32 * KSTR];
    __shared__ uint32_t Vs[2][32 * VSTR];
    __shared__ uint32_t Ps[64 * PSTR];

    const int tid  = threadIdx.x;
    const int wid  = tid >> 5, lane = tid & 31;
    const int g    = lane >> 2, t = lane & 3;
    const int bh   = blockIdx.y;
    const int q0   = blockIdx.x * 64;

    const uint32_t* Qp = g_Q + ((size_t)bh * TSEQ + q0 + wid * 16) * DKH;
    const uint32_t* Kp = g_K + (size_t)bh * TSEQ * DKH;
    const uint32_t* Vp = g_V + (size_t)bh * TSEQ * DKH;

    const uint32_t sK = smem_u32(Ks);
    const uint32_t sV = smem_u32(Vs);

    // Q fragments: 8 k-steps of m16k8 (Q pre-scaled by 0.125 at projection)
    uint32_t qf[8][4];
#pragma unroll
    for (int k8 = 0; k8 < 8; k8++) {
        qf[k8][0] = Qp[g * DKH + k8 * 8 + t];
        qf[k8][1] = Qp[(g + 8) * DKH + k8 * 8 + t];
        qf[k8][2] = Qp[g * DKH + k8 * 8 + t + 4];
        qf[k8][3] = Qp[(g + 8) * DKH + k8 * 8 + t + 4];
    }

    float o[8][4];
#pragma unroll
    for (int i = 0; i < 8; i++)
#pragma unroll
        for (int u = 0; u < 4; u++) o[i][u] = 0.0f;
    float mi0 = -1e30f, mi1 = -1e30f, li0 = 0.0f, li1 = 0.0f;

    auto stageKV = [&](int kt, int pp) {
#pragma unroll
        for (int l = 0; l < 4; l++) {
            int idx = tid + l * 128;          // 512 16B chunks each
            int r = idx >> 4, c = idx & 15;
            cp16(sK + (pp * 32 * KSTR + r * KSTR + c * 4) * 4,
                 Kp + (size_t)(kt * 32 + r) * DKH + c * 4);
            cp16(sV + (pp * 32 * VSTR + r * VSTR + c * 4) * 4,
                 Vp + (size_t)(kt * 32 + r) * DKH + c * 4);
        }
        CP_COMMIT();
    };

    stageKV(0, 0);

    const int NT = TSEQ / 32;   // 64
    for (int kt = 0; kt < NT; kt++) {
        const int p = kt & 1;
        if (kt + 1 < NT) { stageKV(kt + 1, p ^ 1); CP_WAIT1(); }
        else             { CP_WAIT0(); }
        __syncthreads();   // K/V buf p visible to all warps

        // ---- S = Qs @ K^T : 4 n-tiles of m16n8, k=64 ----
        float sacc[4][4];
#pragma unroll
        for (int nt = 0; nt < 4; nt++)
#pragma unroll
            for (int u = 0; u < 4; u++) sacc[nt][u] = 0.0f;

        const uint32_t* kb = Ks[p];
#pragma unroll
        for (int k8 = 0; k8 < 8; k8++) {
#pragma unroll
            for (int nt = 0; nt < 4; nt++) {
                uint32_t b[2];
                b[0] = kb[(nt * 8 + g) * KSTR + k8 * 8 + t];
                b[1] = kb[(nt * 8 + g) * KSTR + k8 * 8 + t + 4];
                mma_tf32(sacc[nt], qf[k8], b);
            }
        }

        // ---- online softmax (rows g and g+8; row spread over 4 lanes) ----
        float r0m = -1e30f, r1m = -1e30f;
#pragma unroll
        for (int nt = 0; nt < 4; nt++) {
            r0m = fmaxf(r0m, fmaxf(sacc[nt][0], sacc[nt][1]));
            r1m = fmaxf(r1m, fmaxf(sacc[nt][2], sacc[nt][3]));
        }
#pragma unroll
        for (int d = 1; d < 4; d <<= 1) {
            r0m = fmaxf(r0m, __shfl_xor_sync(0xffffffffu, r0m, d));
            r1m = fmaxf(r1m, __shfl_xor_sync(0xffffffffu, r1m, d));
        }
        float mn0 = fmaxf(mi0, r0m), mn1 = fmaxf(mi1, r1m);
        float corr0 = __expf(mi0 - mn0), corr1 = __expf(mi1 - mn1);
        mi0 = mn0; mi1 = mn1;

        float rs0 = 0.0f, rs1 = 0.0f;
        uint32_t pb[4][4];
#pragma unroll
        for (int nt = 0; nt < 4; nt++) {
            float p00 = __expf(sacc[nt][0] - mn0);
            float p01 = __expf(sacc[nt][1] - mn0);
            float p10 = __expf(sacc[nt][2] - mn1);
            float p11 = __expf(sacc[nt][3] - mn1);
            rs0 += p00 + p01; rs1 += p10 + p11;
            pb[nt][0] = f2tf32(p00); pb[nt][1] = f2tf32(p01);
            pb[nt][2] = f2tf32(p10); pb[nt][3] = f2tf32(p11);
        }
#pragma unroll
        for (int d = 1; d < 4; d <<= 1) {
            rs0 += __shfl_xor_sync(0xffffffffu, rs0, d);
            rs1 += __shfl_xor_sync(0xffffffffu, rs1, d);
        }
        li0 = li0 * corr0 + rs0;
        li1 = li1 * corr1 + rs1;
#pragma unroll
        for (int nt2 = 0; nt2 < 8; nt2++) {
            o[nt2][0] *= corr0; o[nt2][1] *= corr0;
            o[nt2][2] *= corr1; o[nt2][3] *= corr1;
        }

        // stage P (warp's 16x32 tile) to smem as tf32
        {
            uint32_t* pr = Ps + (wid * 16) * PSTR;
#pragma unroll
            for (int nt = 0; nt < 4; nt++) {
                *(uint2*)(pr + g * PSTR + nt * 8 + 2 * t)       = make_uint2(pb[nt][0], pb[nt][1]);
                *(uint2*)(pr + (g + 8) * PSTR + nt * 8 + 2 * t) = make_uint2(pb[nt][2], pb[nt][3]);
            }
        }
        __syncthreads();   // (also covers: prev PV reads done before overwrite)

        // ---- O += P @ V : 8 n-tiles (dk), k=32 ----
        const uint32_t* pr = Ps + (wid * 16) * PSTR;
        const uint32_t* vb = Vs[p];
#pragma unroll
        for (int kk = 0; kk < 4; kk++) {
            int k0 = kk * 8;
            uint32_t a[4];
            a[0] = pr[g * PSTR + k0 + t];
            a[1] = pr[(g + 8) * PSTR + k0 + t];
            a[2] = pr[g * PSTR + k0 + t + 4];
            a[3] = pr[(g + 8) * PSTR + k0 + t + 4];
#pragma unroll
            for (int nt2 = 0; nt2 < 8; nt2++) {
                uint32_t b[2];
                b[0] = vb[(k0 + t) * VSTR + nt2 * 8 + g];
                b[1] = vb[(k0 + t + 4) * VSTR + nt2 * 8 + g];
                mma_tf32(o[nt2], a, b);
            }
        }
        __syncthreads();   // all warps done with K/V buf p and Ps
    }

    // ---- epilogue: Yc[b, t, h*64+d] = tf32(O / l) ----
    const int b = bh >> 4, h = bh & 15;
    const float inv0 = 1.0f / li0, inv1 = 1.0f / li1;
    const int tr0 = q0 + wid * 16 + g;
#pragma unroll
    for (int nt2 = 0; nt2 < 8; nt2++) {
        int d = h * DKH + nt2 * 8 + 2 * t;
        *(uint2*)(g_Yc + (size_t)(b * TSEQ + tr0) * DMODEL + d)
            = make_uint2(f2tf32(o[nt2][0] * inv0), f2tf32(o[nt2][1] * inv0));
        *(uint2*)(g_Yc + (size_t)(b * TSEQ + tr0 + 8) * DMODEL + d)
            = make_uint2(f2tf32(o[nt2][2] * inv1), f2tf32(o[nt2][3] * inv1));
    }
}

// ---------------------------------------------------------------------------
extern "C" void kernel_launch(void* const* d_in, const int* in_sizes, int n_in,
                              void* d_out, int out_size)
{
    const float* X  = (const float*)d_in[0];
    const float* Wq = (const float*)d_in[1];
    const float* Wk = (const float*)d_in[2];
    const float* Wv = (const float*)d_in[3];
    const float* Wo = (const float*)d_in[4];
    float* out = (float*)d_out;

    const int nX = MTOT * DMODEL, nW = DMODEL * DMODEL;
    conv_tf32<<<nX / 1024, 256>>>(X,  0, nX);
    conv_tf32<<<nW / 1024, 256>>>(Wq, 1, nW);
    conv_tf32<<<nW / 1024, 256>>>(Wk, 2, nW);
    conv_tf32<<<nW / 1024, 256>>>(Wv, 3, nW);
    conv_tf32<<<nW / 1024, 256>>>(Wo, 4, nW);

    dim3 gg(DMODEL / 128, MTOT / 128);   // (8, 64)
    tc_gemm<<<gg, 256>>>(out, 0);   // -> g_Q (tf32, x0.125)
    tc_gemm<<<gg, 256>>>(out, 1);   // -> g_K (tf32)
    tc_gemm<<<gg, 256>>>(out, 2);   // -> g_V (tf32)

    attn_mma<<<dim3(TSEQ / 64, BATCH * NHEAD), 128>>>();   // -> g_Yc (tf32)

    tc_gemm<<<gg, 256>>>(out, 3);   // Yc @ Wo^T -> out (fp32)
}

// round 7
// speedup vs baseline: 3.8921x; 1.1875x over previous
#include <cuda_runtime.h>
#include <cuda_bf16.h>
#include <math.h>
#include <stdint.h>

#define TSEQ   2048
#define BATCH  4
#define NHEAD  16
#define DKH    64
#define DMODEL 1024
#define MTOT   (BATCH*TSEQ)   // 8192

// Scratch (allocation-free). Q/K: tf32 [b,h,t,dk] (Q pre-scaled 0.125).
// V: tf32 TRANSPOSED [b,h,dk,t]. Yc: attention out tf32 [b,t,1024].
__device__ uint32_t g_Q[BATCH*NHEAD*TSEQ*DKH];
__device__ uint32_t g_K[BATCH*NHEAD*TSEQ*DKH];
__device__ uint32_t g_V[BATCH*NHEAD*TSEQ*DKH];
__device__ uint32_t g_Xc[MTOT*DMODEL];
__device__ uint32_t g_Wc[4][DMODEL*DMODEL];
__device__ uint32_t g_Yc[MTOT*DMODEL];

__device__ __forceinline__ uint32_t smem_u32(const void* p) {
    uint32_t a;
    asm("{ .reg .u64 t; cvta.to.shared.u64 t, %1; cvt.u32.u64 %0, t; }" : "=r"(a) : "l"(p));
    return a;
}
__device__ __forceinline__ uint32_t f2tf32(float f) {
    uint32_t r;
    asm("cvt.rna.tf32.f32 %0, %1;" : "=r"(r) : "f"(f));
    return r;
}
__device__ __forceinline__ void cp16(uint32_t dst, const void* src) {
    asm volatile("cp.async.cg.shared.global [%0], [%1], 16;" :: "r"(dst), "l"(src));
}
#define CP_COMMIT() asm volatile("cp.async.commit_group;" ::: "memory")
#define CP_WAIT0()  asm volatile("cp.async.wait_group 0;" ::: "memory")
#define CP_WAIT1()  asm volatile("cp.async.wait_group 1;" ::: "memory")

__device__ __forceinline__ void mma_tf32(float c[4], const uint32_t a[4], const uint32_t b[2]) {
    asm volatile(
        "mma.sync.aligned.m16n8k8.row.col.f32.tf32.tf32.f32 "
        "{%0,%1,%2,%3}, {%4,%5,%6,%7}, {%8,%9}, {%0,%1,%2,%3};"
        : "+f"(c[0]), "+f"(c[1]), "+f"(c[2]), "+f"(c[3])
        : "r"(a[0]), "r"(a[1]), "r"(a[2]), "r"(a[3]), "r"(b[0]), "r"(b[1]));
}
__device__ __forceinline__ void ldm4(uint32_t r[4], uint32_t addr) {
    asm volatile("ldmatrix.sync.aligned.m8n8.x4.shared.b16 {%0,%1,%2,%3}, [%4];"
        : "=r"(r[0]), "=r"(r[1]), "=r"(r[2]), "=r"(r[3]) : "r"(addr));
}

// ===========================================================================
// fp32 -> tf32 (rna) conversions
// ===========================================================================
__global__ __launch_bounds__(256) void conv_x(const float* __restrict__ in)
{
    int i = (blockIdx.x * 256 + threadIdx.x) * 4;
    float4 v = *(const float4*)(in + i);
    *(uint4*)(g_Xc + i) = make_uint4(f2tf32(v.x), f2tf32(v.y), f2tf32(v.z), f2tf32(v.w));
}
__global__ __launch_bounds__(256) void conv_w(const float* __restrict__ w0,
    const float* __restrict__ w1, const float* __restrict__ w2, const float* __restrict__ w3)
{
    const float* src = (blockIdx.y == 0) ? w0 : (blockIdx.y == 1) ? w1
                     : (blockIdx.y == 2) ? w2 : w3;
    int i = (blockIdx.x * 256 + threadIdx.x) * 4;
    float4 v = *(const float4*)(src + i);
    *(uint4*)(g_Wc[blockIdx.y] + i) = make_uint4(f2tf32(v.x), f2tf32(v.y), f2tf32(v.z), f2tf32(v.w));
}

// ===========================================================================
// tf32 mma.sync GEMM with ldmatrix frags: C = A[8192,1024] @ W[1024,1024]^T
// CTA 128x128, BK=16, double-buffered cp.async, 8 warps 2x4, warp 64x32.
// mode 0/1: tf32 scatter [b,h,t,dk]; mode 2: tf32 scatter TRANSPOSED
// [b,h,dk,t]; mode 3: fp32 row-major out.
// ===========================================================================
#define SSTRIDE 20

__global__ __launch_bounds__(256) void tc_gemm(float* __restrict__ Cout, int mode)
{
    __shared__ uint32_t As[2][128 * SSTRIDE];
    __shared__ uint32_t Bs[2][128 * SSTRIDE];

    const uint32_t* A = (mode == 3) ? g_Yc : g_Xc;
    const uint32_t* W = g_Wc[mode];

    const int tid  = threadIdx.x;
    const int wid  = tid >> 5, lane = tid & 31;
    const int g    = lane >> 2, t = lane & 3;
    const int wm   = (wid >> 2) * 64;
    const int wn   = (wid & 3) * 32;
    const int m0   = blockIdx.y * 128;
    const int n0   = blockIdx.x * 128;

    // ldmatrix per-lane row/col selectors
    const int arow = (lane & 7) + ((lane >> 3) & 1) * 8;   // A: m-row offset
    const int acol = (lane >> 4) * 4;                      // A: k-col offset
    const int brow = (lane & 7) + ((lane >> 4) ? 8 : 0);   // B: n-row offset
    const int bcol = ((lane >> 3) & 1) * 4;                // B: k-col offset

    const uint32_t sA = smem_u32(As);
    const uint32_t sB = smem_u32(Bs);
    const int r0 = tid >> 2, c4 = tid & 3;

    float acc[4][4][4];
#pragma unroll
    for (int i = 0; i < 4; i++)
#pragma unroll
        for (int j = 0; j < 4; j++)
#pragma unroll
            for (int u = 0; u < 4; u++) acc[i][j][u] = 0.0f;

    auto stage = [&](int kb, int p) {
#pragma unroll
        for (int h = 0; h < 2; h++) {
            int row = r0 + h * 64;
            cp16(sA + (p * 128 * SSTRIDE + row * SSTRIDE + c4 * 4) * 4,
                 A + (size_t)(m0 + row) * DMODEL + kb * 16 + c4 * 4);
            cp16(sB + (p * 128 * SSTRIDE + row * SSTRIDE + c4 * 4) * 4,
                 W + (size_t)(n0 + row) * DMODEL + kb * 16 + c4 * 4);
        }
        CP_COMMIT();
    };

    stage(0, 0);

    const int NT = DMODEL / 16;
    for (int kb = 0; kb < NT; kb++) {
        const int p = kb & 1;
        CP_WAIT0();
        __syncthreads();           // buf p full AND all warps done with buf p (prev round)
        if (kb + 1 < NT) stage(kb + 1, p ^ 1);

        const uint32_t sAp = sA + p * 128 * SSTRIDE * 4;
        const uint32_t sBp = sB + p * 128 * SSTRIDE * 4;
#pragma unroll
        for (int k8 = 0; k8 < 2; k8++) {
            uint32_t a[4][4], b[4][2];
#pragma unroll
            for (int mt = 0; mt < 4; mt++)
                ldm4(a[mt], sAp + ((wm + mt * 16 + arow) * SSTRIDE + k8 * 8 + acol) * 4);
#pragma unroll
            for (int g2 = 0; g2 < 2; g2++) {
                uint32_t t4[4];
                ldm4(t4, sBp + ((wn + g2 * 16 + brow) * SSTRIDE + k8 * 8 + bcol) * 4);
                b[g2 * 2][0] = t4[0]; b[g2 * 2][1] = t4[1];
                b[g2 * 2 + 1][0] = t4[2]; b[g2 * 2 + 1][1] = t4[3];
            }
#pragma unroll
            for (int mt = 0; mt < 4; mt++)
#pragma unroll
                for (int nt = 0; nt < 4; nt++)
                    mma_tf32(acc[mt][nt], a[mt], b[nt]);
        }
    }

#pragma unroll
    for (int mt = 0; mt < 4; mt++) {
#pragma unroll
        for (int h = 0; h < 2; h++) {
            int m = m0 + wm + mt * 16 + g + h * 8;
#pragma unroll
            for (int nt = 0; nt < 4; nt++) {
                int n = n0 + wn + nt * 8 + 2 * t;
                float vx = acc[mt][nt][h * 2 + 0];
                float vy = acc[mt][nt][h * 2 + 1];
                int b = m >> 11, tt = m & (TSEQ - 1);
                int hh = n >> 6, dk0 = n & 63;
                if (mode == 3) {
                    *(float2*)(Cout + (size_t)m * DMODEL + n) = make_float2(vx, vy);
                } else if (mode == 2) {   // V transposed: [b,h,dk,t]
                    uint32_t* base = g_V + ((size_t)(b * NHEAD + hh) * DKH + dk0) * TSEQ + tt;
                    base[0]    = f2tf32(vx);
                    base[TSEQ] = f2tf32(vy);
                } else {
                    if (mode == 0) { vx *= 0.125f; vy *= 0.125f; }
                    uint32_t* base = (mode == 0) ? g_Q : g_K;
                    *(uint2*)(base + ((size_t)(b * NHEAD + hh) * TSEQ + tt) * DKH + dk0)
                        = make_uint2(f2tf32(vx), f2tf32(vy));
                }
            }
        }
    }
}

// ===========================================================================
// Tensor-core flash attention, ldmatrix everywhere. Per (b,h): BM=64 q rows
// (4 warps x m16), BN=32 keys/iter, dk=64. V in smem is [dk=64][t=32].
// ===========================================================================
#define KSTR 68
#define VSTR 36
#define PSTR 36

__global__ __launch_bounds__(128) void attn_mma()
{
    __shared__ uint32_t Ks[2][32 * KSTR];
    __shared__ uint32_t Vs[2][64 * VSTR];
    __shared__ uint32_t Ps[64 * PSTR];

    const int tid  = threadIdx.x;
    const int wid  = tid >> 5, lane = tid & 31;
    const int g    = lane >> 2, t = lane & 3;
    const int bh   = blockIdx.y;
    const int q0   = blockIdx.x * 64;

    const int arow = (lane & 7) + ((lane >> 3) & 1) * 8;
    const int acol = (lane >> 4) * 4;
    const int brow = (lane & 7) + ((lane >> 4) ? 8 : 0);
    const int bcol = ((lane >> 3) & 1) * 4;

    const uint32_t* Qp = g_Q + ((size_t)bh * TSEQ + q0 + wid * 16) * DKH;
    const uint32_t* Kp = g_K + (size_t)bh * TSEQ * DKH;
    const uint32_t* Vp = g_V + (size_t)bh * DKH * TSEQ;   // [dk][t]

    const uint32_t sK = smem_u32(Ks);
    const uint32_t sV = smem_u32(Vs);
    const uint32_t sP = smem_u32(Ps);

    uint32_t qf[8][4];
#pragma unroll
    for (int k8 = 0; k8 < 8; k8++) {
        qf[k8][0] = Qp[g * DKH + k8 * 8 + t];
        qf[k8][1] = Qp[(g + 8) * DKH + k8 * 8 + t];
        qf[k8][2] = Qp[g * DKH + k8 * 8 + t + 4];
        qf[k8][3] = Qp[(g + 8) * DKH + k8 * 8 + t + 4];
    }

    float o[8][4];
#pragma unroll
    for (int i = 0; i < 8; i++)
#pragma unroll
        for (int u = 0; u < 4; u++) o[i][u] = 0.0f;
    float mi0 = -1e30f, mi1 = -1e30f, li0 = 0.0f, li1 = 0.0f;

    auto stageKV = [&](int kt, int pp) {
        // K: 32 rows x 64 words ([t][dk])
#pragma unroll
        for (int l = 0; l < 4; l++) {
            int idx = tid + l * 128;
            int r = idx >> 4, c = idx & 15;
            cp16(sK + (pp * 32 * KSTR + r * KSTR + c * 4) * 4,
                 Kp + (size_t)(kt * 32 + r) * DKH + c * 4);
        }
        // V: 64 rows x 32 words ([dk][t])
#pragma unroll
        for (int l = 0; l < 4; l++) {
            int idx = tid + l * 128;
            int r = idx >> 3, c = idx & 7;
            cp16(sV + (pp * 64 * VSTR + r * VSTR + c * 4) * 4,
                 Vp + (size_t)r * TSEQ + kt * 32 + c * 4);
        }
        CP_COMMIT();
    };

    stageKV(0, 0);

    const int NT = TSEQ / 32;
    for (int kt = 0; kt < NT; kt++) {
        const int p = kt & 1;
        if (kt + 1 < NT) { stageKV(kt + 1, p ^ 1); CP_WAIT1(); }
        else             { CP_WAIT0(); }
        __syncthreads();

        // ---- S = Q @ K^T ----
        float sacc[4][4];
#pragma unroll
        for (int nt = 0; nt < 4; nt++)
#pragma unroll
            for (int u = 0; u < 4; u++) sacc[nt][u] = 0.0f;

        const uint32_t sKp = sK + p * 32 * KSTR * 4;
#pragma unroll
        for (int k8 = 0; k8 < 8; k8++) {
            uint32_t b[4][2];
#pragma unroll
            for (int g2 = 0; g2 < 2; g2++) {
                uint32_t t4[4];
                ldm4(t4, sKp + ((g2 * 16 + brow) * KSTR + k8 * 8 + bcol) * 4);
                b[g2 * 2][0] = t4[0]; b[g2 * 2][1] = t4[1];
                b[g2 * 2 + 1][0] = t4[2]; b[g2 * 2 + 1][1] = t4[3];
            }
#pragma unroll
            for (int nt = 0; nt < 4; nt++)
                mma_tf32(sacc[nt], qf[k8], b[nt]);
        }

        // ---- online softmax ----
        float r0m = -1e30f, r1m = -1e30f;
#pragma unroll
        for (int nt = 0; nt < 4; nt++) {
            r0m = fmaxf(r0m, fmaxf(sacc[nt][0], sacc[nt][1]));
            r1m = fmaxf(r1m, fmaxf(sacc[nt][2], sacc[nt][3]));
        }
#pragma unroll
        for (int d = 1; d < 4; d <<= 1) {
            r0m = fmaxf(r0m, __shfl_xor_sync(0xffffffffu, r0m, d));
            r1m = fmaxf(r1m, __shfl_xor_sync(0xffffffffu, r1m, d));
        }
        float mn0 = fmaxf(mi0, r0m), mn1 = fmaxf(mi1, r1m);
        float corr0 = __expf(mi0 - mn0), corr1 = __expf(mi1 - mn1);
        mi0 = mn0; mi1 = mn1;

        float rs0 = 0.0f, rs1 = 0.0f;
        uint32_t pb[4][4];
#pragma unroll
        for (int nt = 0; nt < 4; nt++) {
            float p00 = __expf(sacc[nt][0] - mn0);
            float p01 = __expf(sacc[nt][1] - mn0);
            float p10 = __expf(sacc[nt][2] - mn1);
            float p11 = __expf(sacc[nt][3] - mn1);
            rs0 += p00 + p01; rs1 += p10 + p11;
            pb[nt][0] = f2tf32(p00); pb[nt][1] = f2tf32(p01);
            pb[nt][2] = f2tf32(p10); pb[nt][3] = f2tf32(p11);
        }
#pragma unroll
        for (int d = 1; d < 4; d <<= 1) {
            rs0 += __shfl_xor_sync(0xffffffffu, rs0, d);
            rs1 += __shfl_xor_sync(0xffffffffu, rs1, d);
        }
        li0 = li0 * corr0 + rs0;
        li1 = li1 * corr1 + rs1;
#pragma unroll
        for (int nt2 = 0; nt2 < 8; nt2++) {
            o[nt2][0] *= corr0; o[nt2][1] *= corr0;
            o[nt2][2] *= corr1; o[nt2][3] *= corr1;
        }

        // stage P tile (16x32 per warp) as tf32
        {
            uint32_t* pr = Ps + (wid * 16) * PSTR;
#pragma unroll
            for (int nt = 0; nt < 4; nt++) {
                *(uint2*)(pr + g * PSTR + nt * 8 + 2 * t)       = make_uint2(pb[nt][0], pb[nt][1]);
                *(uint2*)(pr + (g + 8) * PSTR + nt * 8 + 2 * t) = make_uint2(pb[nt][2], pb[nt][3]);
            }
        }
        __syncthreads();

        // ---- O += P @ V ----
        const uint32_t sPp = sP + (wid * 16) * PSTR * 4;
        const uint32_t sVp = sV + p * 64 * VSTR * 4;
#pragma unroll
        for (int kk = 0; kk < 4; kk++) {
            int k0 = kk * 8;
            uint32_t a[4];
            ldm4(a, sPp + (arow * PSTR + k0 + acol) * 4);
            uint32_t bb[8][2];
#pragma unroll
            for (int g2 = 0; g2 < 4; g2++) {
                uint32_t t4[4];
                ldm4(t4, sVp + ((g2 * 16 + brow) * VSTR + k0 + bcol) * 4);
                bb[g2 * 2][0] = t4[0]; bb[g2 * 2][1] = t4[1];
                bb[g2 * 2 + 1][0] = t4[2]; bb[g2 * 2 + 1][1] = t4[3];
            }
#pragma unroll
            for (int nt2 = 0; nt2 < 8; nt2++)
                mma_tf32(o[nt2], a, bb[nt2]);
        }
        __syncthreads();
    }

    // ---- epilogue: Yc = tf32(O / l) ----
    const int b = bh >> 4, h = bh & 15;
    const float inv0 = 1.0f / li0, inv1 = 1.0f / li1;
    const int tr0 = q0 + wid * 16 + g;
#pragma unroll
    for (int nt2 = 0; nt2 < 8; nt2++) {
        int d = h * DKH + nt2 * 8 + 2 * t;
        *(uint2*)(g_Yc + (size_t)(b * TSEQ + tr0) * DMODEL + d)
            = make_uint2(f2tf32(o[nt2][0] * inv0), f2tf32(o[nt2][1] * inv0));
        *(uint2*)(g_Yc + (size_t)(b * TSEQ + tr0 + 8) * DMODEL + d)
            = make_uint2(f2tf32(o[nt2][2] * inv1), f2tf32(o[nt2][3] * inv1));
    }
}

// ---------------------------------------------------------------------------
extern "C" void kernel_launch(void* const* d_in, const int* in_sizes, int n_in,
                              void* d_out, int out_size)
{
    const float* X  = (const float*)d_in[0];
    const float* Wq = (const float*)d_in[1];
    const float* Wk = (const float*)d_in[2];
    const float* Wv = (const float*)d_in[3];
    const float* Wo = (const float*)d_in[4];
    float* out = (float*)d_out;

    const int nX = MTOT * DMODEL, nW = DMODEL * DMODEL;
    conv_x<<<nX / 1024, 256>>>(X);
    conv_w<<<dim3(nW / 1024, 4), 256>>>(Wq, Wk, Wv, Wo);

    dim3 gg(DMODEL / 128, MTOT / 128);   // (8, 64)
    tc_gemm<<<gg, 256>>>(out, 0);   // -> g_Q (tf32, x0.125)
    tc_gemm<<<gg, 256>>>(out, 1);   // -> g_K (tf32)
    tc_gemm<<<gg, 256>>>(out, 2);   // -> g_V (tf32, transposed)

    attn_mma<<<dim3(TSEQ / 64, BATCH * NHEAD), 128>>>();   // -> g_Yc

    tc_gemm<<<gg, 256>>>(out, 3);   // Yc @ Wo^T -> out (fp32)
}

// round 8
// speedup vs baseline: 3.8922x; 1.0000x over previous
#include <cuda_runtime.h>
#include <cuda_bf16.h>
#include <math.h>
#include <stdint.h>

#define TSEQ   2048
#define BATCH  4
#define NHEAD  16
#define DKH    64
#define DMODEL 1024
#define MTOT   (BATCH*TSEQ)   // 8192

// Scratch (allocation-free). Q/K: tf32 [b,h,t,dk] (Q pre-scaled 0.125).
// V: tf32 TRANSPOSED [b,h,dk,t]. Yc: attention out tf32 [b,t,1024].
__device__ uint32_t g_Q[BATCH*NHEAD*TSEQ*DKH];
__device__ uint32_t g_K[BATCH*NHEAD*TSEQ*DKH];
__device__ uint32_t g_V[BATCH*NHEAD*TSEQ*DKH];
__device__ uint32_t g_Xc[MTOT*DMODEL];
__device__ uint32_t g_Wc[4][DMODEL*DMODEL];
__device__ uint32_t g_Yc[MTOT*DMODEL];

__device__ __forceinline__ uint32_t smem_u32(const void* p) {
    uint32_t a;
    asm("{ .reg .u64 t; cvta.to.shared.u64 t, %1; cvt.u32.u64 %0, t; }" : "=r"(a) : "l"(p));
    return a;
}
__device__ __forceinline__ uint32_t f2tf32(float f) {
    uint32_t r;
    asm("cvt.rna.tf32.f32 %0, %1;" : "=r"(r) : "f"(f));
    return r;
}
__device__ __forceinline__ void cp16(uint32_t dst, const void* src) {
    asm volatile("cp.async.cg.shared.global [%0], [%1], 16;" :: "r"(dst), "l"(src));
}
#define CP_COMMIT() asm volatile("cp.async.commit_group;" ::: "memory")
#define CP_WAIT0()  asm volatile("cp.async.wait_group 0;" ::: "memory")
#define CP_WAIT1()  asm volatile("cp.async.wait_group 1;" ::: "memory")

__device__ __forceinline__ void mma_tf32(float c[4], const uint32_t a[4], const uint32_t b[2]) {
    asm volatile(
        "mma.sync.aligned.m16n8k8.row.col.f32.tf32.tf32.f32 "
        "{%0,%1,%2,%3}, {%4,%5,%6,%7}, {%8,%9}, {%0,%1,%2,%3};"
        : "+f"(c[0]), "+f"(c[1]), "+f"(c[2]), "+f"(c[3])
        : "r"(a[0]), "r"(a[1]), "r"(a[2]), "r"(a[3]), "r"(b[0]), "r"(b[1]));
}
__device__ __forceinline__ void ldm4(uint32_t r[4], uint32_t addr) {
    asm volatile("ldmatrix.sync.aligned.m8n8.x4.shared.b16 {%0,%1,%2,%3}, [%4];"
        : "=r"(r[0]), "=r"(r[1]), "=r"(r[2]), "=r"(r[3]) : "r"(addr));
}

// ===========================================================================
// fp32 -> tf32 (rna) conversions
// ===========================================================================
__global__ __launch_bounds__(256) void conv_x(const float* __restrict__ in)
{
    int i = (blockIdx.x * 256 + threadIdx.x) * 4;
    float4 v = *(const float4*)(in + i);
    *(uint4*)(g_Xc + i) = make_uint4(f2tf32(v.x), f2tf32(v.y), f2tf32(v.z), f2tf32(v.w));
}
__global__ __launch_bounds__(256) void conv_w(const float* __restrict__ w0,
    const float* __restrict__ w1, const float* __restrict__ w2, const float* __restrict__ w3)
{
    const float* src = (blockIdx.y == 0) ? w0 : (blockIdx.y == 1) ? w1
                     : (blockIdx.y == 2) ? w2 : w3;
    int i = (blockIdx.x * 256 + threadIdx.x) * 4;
    float4 v = *(const float4*)(src + i);
    *(uint4*)(g_Wc[blockIdx.y] + i) = make_uint4(f2tf32(v.x), f2tf32(v.y), f2tf32(v.z), f2tf32(v.w));
}

// ===========================================================================
// tf32 mma.sync GEMM with ldmatrix frags: C = A[8192,1024] @ W[1024,1024]^T
// CTA 128x128, BK=16, double-buffered cp.async, 8 warps 2x4, warp 64x32.
// mode 0/1: tf32 scatter [b,h,t,dk]; mode 2: tf32 scatter TRANSPOSED
// [b,h,dk,t]; mode 3: fp32 row-major out.
// ===========================================================================
#define SSTRIDE 20

__global__ __launch_bounds__(256) void tc_gemm(float* __restrict__ Cout, int mode)
{
    __shared__ uint32_t As[2][128 * SSTRIDE];
    __shared__ uint32_t Bs[2][128 * SSTRIDE];

    const uint32_t* A = (mode == 3) ? g_Yc : g_Xc;
    const uint32_t* W = g_Wc[mode];

    const int tid  = threadIdx.x;
    const int wid  = tid >> 5, lane = tid & 31;
    const int g    = lane >> 2, t = lane & 3;
    const int wm   = (wid >> 2) * 64;
    const int wn   = (wid & 3) * 32;
    const int m0   = blockIdx.y * 128;
    const int n0   = blockIdx.x * 128;

    // ldmatrix per-lane row/col selectors
    const int arow = (lane & 7) + ((lane >> 3) & 1) * 8;   // A: m-row offset
    const int acol = (lane >> 4) * 4;                      // A: k-col offset
    const int brow = (lane & 7) + ((lane >> 4) ? 8 : 0);   // B: n-row offset
    const int bcol = ((lane >> 3) & 1) * 4;                // B: k-col offset

    const uint32_t sA = smem_u32(As);
    const uint32_t sB = smem_u32(Bs);
    const int r0 = tid >> 2, c4 = tid & 3;

    float acc[4][4][4];
#pragma unroll
    for (int i = 0; i < 4; i++)
#pragma unroll
        for (int j = 0; j < 4; j++)
#pragma unroll
            for (int u = 0; u < 4; u++) acc[i][j][u] = 0.0f;

    auto stage = [&](int kb, int p) {
#pragma unroll
        for (int h = 0; h < 2; h++) {
            int row = r0 + h * 64;
            cp16(sA + (p * 128 * SSTRIDE + row * SSTRIDE + c4 * 4) * 4,
                 A + (size_t)(m0 + row) * DMODEL + kb * 16 + c4 * 4);
            cp16(sB + (p * 128 * SSTRIDE + row * SSTRIDE + c4 * 4) * 4,
                 W + (size_t)(n0 + row) * DMODEL + kb * 16 + c4 * 4);
        }
        CP_COMMIT();
    };

    stage(0, 0);

    const int NT = DMODEL / 16;
    for (int kb = 0; kb < NT; kb++) {
        const int p = kb & 1;
        CP_WAIT0();
        __syncthreads();           // buf p full AND all warps done with buf p (prev round)
        if (kb + 1 < NT) stage(kb + 1, p ^ 1);

        const uint32_t sAp = sA + p * 128 * SSTRIDE * 4;
        const uint32_t sBp = sB + p * 128 * SSTRIDE * 4;
#pragma unroll
        for (int k8 = 0; k8 < 2; k8++) {
            uint32_t a[4][4], b[4][2];
#pragma unroll
            for (int mt = 0; mt < 4; mt++)
                ldm4(a[mt], sAp + ((wm + mt * 16 + arow) * SSTRIDE + k8 * 8 + acol) * 4);
#pragma unroll
            for (int g2 = 0; g2 < 2; g2++) {
                uint32_t t4[4];
                ldm4(t4, sBp + ((wn + g2 * 16 + brow) * SSTRIDE + k8 * 8 + bcol) * 4);
                b[g2 * 2][0] = t4[0]; b[g2 * 2][1] = t4[1];
                b[g2 * 2 + 1][0] = t4[2]; b[g2 * 2 + 1][1] = t4[3];
            }
#pragma unroll
            for (int mt = 0; mt < 4; mt++)
#pragma unroll
                for (int nt = 0; nt < 4; nt++)
                    mma_tf32(acc[mt][nt], a[mt], b[nt]);
        }
    }

#pragma unroll
    for (int mt = 0; mt < 4; mt++) {
#pragma unroll
        for (int h = 0; h < 2; h++) {
            int m = m0 + wm + mt * 16 + g + h * 8;
#pragma unroll
            for (int nt = 0; nt < 4; nt++) {
                int n = n0 + wn + nt * 8 + 2 * t;
                float vx = acc[mt][nt][h * 2 + 0];
                float vy = acc[mt][nt][h * 2 + 1];
                int b = m >> 11, tt = m & (TSEQ - 1);
                int hh = n >> 6, dk0 = n & 63;
                if (mode == 3) {
                    *(float2*)(Cout + (size_t)m * DMODEL + n) = make_float2(vx, vy);
                } else if (mode == 2) {   // V transposed: [b,h,dk,t]
                    uint32_t* base = g_V + ((size_t)(b * NHEAD + hh) * DKH + dk0) * TSEQ + tt;
                    base[0]    = f2tf32(vx);
                    base[TSEQ] = f2tf32(vy);
                } else {
                    if (mode == 0) { vx *= 0.125f; vy *= 0.125f; }
                    uint32_t* base = (mode == 0) ? g_Q : g_K;
                    *(uint2*)(base + ((size_t)(b * NHEAD + hh) * TSEQ + tt) * DKH + dk0)
                        = make_uint2(f2tf32(vx), f2tf32(vy));
                }
            }
        }
    }
}

// ===========================================================================
// Tensor-core flash attention, ldmatrix everywhere. Per (b,h): BM=64 q rows
// (4 warps x m16), BN=32 keys/iter, dk=64. V in smem is [dk=64][t=32].
// ===========================================================================
#define KSTR 68
#define VSTR 36
#define PSTR 36

__global__ __launch_bounds__(128) void attn_mma()
{
    __shared__ uint32_t Ks[2][32 * KSTR];
    __shared__ uint32_t Vs[2][64 * VSTR];
    __shared__ uint32_t Ps[64 * PSTR];

    const int tid  = threadIdx.x;
    const int wid  = tid >> 5, lane = tid & 31;
    const int g    = lane >> 2, t = lane & 3;
    const int bh   = blockIdx.y;
    const int q0   = blockIdx.x * 64;

    const int arow = (lane & 7) + ((lane >> 3) & 1) * 8;
    const int acol = (lane >> 4) * 4;
    const int brow = (lane & 7) + ((lane >> 4) ? 8 : 0);
    const int bcol = ((lane >> 3) & 1) * 4;

    const uint32_t* Qp = g_Q + ((size_t)bh * TSEQ + q0 + wid * 16) * DKH;
    const uint32_t* Kp = g_K + (size_t)bh * TSEQ * DKH;
    const uint32_t* Vp = g_V + (size_t)bh * DKH * TSEQ;   // [dk][t]

    const uint32_t sK = smem_u32(Ks);
    const uint32_t sV = smem_u32(Vs);
    const uint32_t sP = smem_u32(Ps);

    uint32_t qf[8][4];
#pragma unroll
    for (int k8 = 0; k8 < 8; k8++) {
        qf[k8][0] = Qp[g * DKH + k8 * 8 + t];
        qf[k8][1] = Qp[(g + 8) * DKH + k8 * 8 + t];
        qf[k8][2] = Qp[g * DKH + k8 * 8 + t + 4];
        qf[k8][3] = Qp[(g + 8) * DKH + k8 * 8 + t + 4];
    }

    float o[8][4];
#pragma unroll
    for (int i = 0; i < 8; i++)
#pragma unroll
        for (int u = 0; u < 4; u++) o[i][u] = 0.0f;
    float mi0 = -1e30f, mi1 = -1e30f, li0 = 0.0f, li1 = 0.0f;

    auto stageKV = [&](int kt, int pp) {
        // K: 32 rows x 64 words ([t][dk])
#pragma unroll
        for (int l = 0; l < 4; l++) {
            int idx = tid + l * 128;
            int r = idx >> 4, c = idx & 15;
            cp16(sK + (pp * 32 * KSTR + r * KSTR + c * 4) * 4,
                 Kp + (size_t)(kt * 32 + r) * DKH + c * 4);
        }
        // V: 64 rows x 32 words ([dk][t])
#pragma unroll
        for (int l = 0; l < 4; l++) {
            int idx = tid + l * 128;
            int r = idx >> 3, c = idx & 7;
            cp16(sV + (pp * 64 * VSTR + r * VSTR + c * 4) * 4,
                 Vp + (size_t)r * TSEQ + kt * 32 + c * 4);
        }
        CP_COMMIT();
    };

    stageKV(0, 0);

    const int NT = TSEQ / 32;
    for (int kt = 0; kt < NT; kt++) {
        const int p = kt & 1;
        if (kt + 1 < NT) { stageKV(kt + 1, p ^ 1); CP_WAIT1(); }
        else             { CP_WAIT0(); }
        __syncthreads();

        // ---- S = Q @ K^T ----
        float sacc[4][4];
#pragma unroll
        for (int nt = 0; nt < 4; nt++)
#pragma unroll
            for (int u = 0; u < 4; u++) sacc[nt][u] = 0.0f;

        const uint32_t sKp = sK + p * 32 * KSTR * 4;
#pragma unroll
        for (int k8 = 0; k8 < 8; k8++) {
            uint32_t b[4][2];
#pragma unroll
            for (int g2 = 0; g2 < 2; g2++) {
                uint32_t t4[4];
                ldm4(t4, sKp + ((g2 * 16 + brow) * KSTR + k8 * 8 + bcol) * 4);
                b[g2 * 2][0] = t4[0]; b[g2 * 2][1] = t4[1];
                b[g2 * 2 + 1][0] = t4[2]; b[g2 * 2 + 1][1] = t4[3];
            }
#pragma unroll
            for (int nt = 0; nt < 4; nt++)
                mma_tf32(sacc[nt], qf[k8], b[nt]);
        }

        // ---- online softmax ----
        float r0m = -1e30f, r1m = -1e30f;
#pragma unroll
        for (int nt = 0; nt < 4; nt++) {
            r0m = fmaxf(r0m, fmaxf(sacc[nt][0], sacc[nt][1]));
            r1m = fmaxf(r1m, fmaxf(sacc[nt][2], sacc[nt][3]));
        }
#pragma unroll
        for (int d = 1; d < 4; d <<= 1) {
            r0m = fmaxf(r0m, __shfl_xor_sync(0xffffffffu, r0m, d));
            r1m = fmaxf(r1m, __shfl_xor_sync(0xffffffffu, r1m, d));
        }
        float mn0 = fmaxf(mi0, r0m), mn1 = fmaxf(mi1, r1m);
        float corr0 = __expf(mi0 - mn0), corr1 = __expf(mi1 - mn1);
        mi0 = mn0; mi1 = mn1;

        float rs0 = 0.0f, rs1 = 0.0f;
        uint32_t pb[4][4];
#pragma unroll
        for (int nt = 0; nt < 4; nt++) {
            float p00 = __expf(sacc[nt][0] - mn0);
            float p01 = __expf(sacc[nt][1] - mn0);
            float p10 = __expf(sacc[nt][2] - mn1);
            float p11 = __expf(sacc[nt][3] - mn1);
            rs0 += p00 + p01; rs1 += p10 + p11;
            pb[nt][0] = f2tf32(p00); pb[nt][1] = f2tf32(p01);
            pb[nt][2] = f2tf32(p10); pb[nt][3] = f2tf32(p11);
        }
#pragma unroll
        for (int d = 1; d < 4; d <<= 1) {
            rs0 += __shfl_xor_sync(0xffffffffu, rs0, d);
            rs1 += __shfl_xor_sync(0xffffffffu, rs1, d);
        }
        li0 = li0 * corr0 + rs0;
        li1 = li1 * corr1 + rs1;
#pragma unroll
        for (int nt2 = 0; nt2 < 8; nt2++) {
            o[nt2][0] *= corr0; o[nt2][1] *= corr0;
            o[nt2][2] *= corr1; o[nt2][3] *= corr1;
        }

        // stage P tile (16x32 per warp) as tf32
        {
            uint32_t* pr = Ps + (wid * 16) * PSTR;
#pragma unroll
            for (int nt = 0; nt < 4; nt++) {
                *(uint2*)(pr + g * PSTR + nt * 8 + 2 * t)       = make_uint2(pb[nt][0], pb[nt][1]);
                *(uint2*)(pr + (g + 8) * PSTR + nt * 8 + 2 * t) = make_uint2(pb[nt][2], pb[nt][3]);
            }
        }
        __syncthreads();

        // ---- O += P @ V ----
        const uint32_t sPp = sP + (wid * 16) * PSTR * 4;
        const uint32_t sVp = sV + p * 64 * VSTR * 4;
#pragma unroll
        for (int kk = 0; kk < 4; kk++) {
            int k0 = kk * 8;
            uint32_t a[4];
            ldm4(a, sPp + (arow * PSTR + k0 + acol) * 4);
            uint32_t bb[8][2];
#pragma unroll
            for (int g2 = 0; g2 < 4; g2++) {
                uint32_t t4[4];
                ldm4(t4, sVp + ((g2 * 16 + brow) * VSTR + k0 + bcol) * 4);
                bb[g2 * 2][0] = t4[0]; bb[g2 * 2][1] = t4[1];
                bb[g2 * 2 + 1][0] = t4[2]; bb[g2 * 2 + 1][1] = t4[3];
            }
#pragma unroll
            for (int nt2 = 0; nt2 < 8; nt2++)
                mma_tf32(o[nt2], a, bb[nt2]);
        }
        __syncthreads();
    }

    // ---- epilogue: Yc = tf32(O / l) ----
    const int b = bh >> 4, h = bh & 15;
    const float inv0 = 1.0f / li0, inv1 = 1.0f / li1;
    const int tr0 = q0 + wid * 16 + g;
#pragma unroll
    for (int nt2 = 0; nt2 < 8; nt2++) {
        int d = h * DKH + nt2 * 8 + 2 * t;
        *(uint2*)(g_Yc + (size_t)(b * TSEQ + tr0) * DMODEL + d)
            = make_uint2(f2tf32(o[nt2][0] * inv0), f2tf32(o[nt2][1] * inv0));
        *(uint2*)(g_Yc + (size_t)(b * TSEQ + tr0 + 8) * DMODEL + d)
            = make_uint2(f2tf32(o[nt2][2] * inv1), f2tf32(o[nt2][3] * inv1));
    }
}

// ---------------------------------------------------------------------------
extern "C" void kernel_launch(void* const* d_in, const int* in_sizes, int n_in,
                              void* d_out, int out_size)
{
    const float* X  = (const float*)d_in[0];
    const float* Wq = (const float*)d_in[1];
    const float* Wk = (const float*)d_in[2];
    const float* Wv = (const float*)d_in[3];
    const float* Wo = (const float*)d_in[4];
    float* out = (float*)d_out;

    const int nX = MTOT * DMODEL, nW = DMODEL * DMODEL;
    conv_x<<<nX / 1024, 256>>>(X);
    conv_w<<<dim3(nW / 1024, 4), 256>>>(Wq, Wk, Wv, Wo);

    dim3 gg(DMODEL / 128, MTOT / 128);   // (8, 64)
    tc_gemm<<<gg, 256>>>(out, 0);   // -> g_Q (tf32, x0.125)
    tc_gemm<<<gg, 256>>>(out, 1);   // -> g_K (tf32)
    tc_gemm<<<gg, 256>>>(out, 2);   // -> g_V (tf32, transposed)

    attn_mma<<<dim3(TSEQ / 64, BATCH * NHEAD), 128>>>();   // -> g_Yc

    tc_gemm<<<gg, 256>>>(out, 3);   // Yc @ Wo^T -> out (fp32)
}